// round 2
// baseline (speedup 1.0000x reference)
#include <cuda_runtime.h>
#include <math.h>

#define KP 4096
#define BP 8
#define THREADS 256
#define TILE_I 256          // i-points per block
#define IPT 4               // i-points per thread
#define JSEG 4              // j-range split across lanes within a tile
#define TILE_J 1024         // j-points per smem tile
#define NTILE (KP / TILE_J) // 4
#define JLEN (TILE_J / JSEG) // 256 j per lane per tile
#define SMEM_BYTES (4 * TILE_J * 4)   // 4 SoA arrays of 1024 floats = 16 KB

#define W_CHAMFER 5.0f
#define W_KNN 3.0f
#define ALPHA 1.05f

// Scratch (no allocations allowed)
__device__ float g_cham[BP * KP];
__device__ float g_value[BP * KP];
__device__ float g_batch[BP];

// Insert d into ascending sorted 6-array (keeps 6 smallest).
__device__ __forceinline__ void heap_insert(float (&h)[6], float d) {
    if (d < h[5]) {
        h[5] = d;
#pragma unroll
        for (int m = 5; m >= 1; --m) {
            float lo = fminf(h[m - 1], h[m]);
            float hi = fmaxf(h[m - 1], h[m]);
            h[m - 1] = lo;
            h[m] = hi;
        }
    }
}

__global__ void __launch_bounds__(THREADS)
dist_kernel(const float* __restrict__ adv, const float* __restrict__ ori) {
    extern __shared__ float sm[];
    float* s_x = sm;
    float* s_y = sm + TILE_J;
    float* s_z = sm + 2 * TILE_J;
    float* s_s = sm + 3 * TILE_J;

    const int b = blockIdx.y;
    const int tid = threadIdx.x;
    const float* A = adv + (size_t)b * KP * 3;
    const float* O = ori + (size_t)b * KP * 3;

    const int ig  = tid >> 2;     // 64 i-groups per block
    const int seg = tid & 3;      // j-segment within tile
    const int ibase = blockIdx.x * TILE_I + ig * IPT;

    float mx[IPT], my[IPT], mz[IPT], ci[IPT], cmin[IPT];
    float h[IPT][6];
#pragma unroll
    for (int k = 0; k < IPT; ++k) {
        int il = ibase + k;
        float x = A[3 * il + 0], y = A[3 * il + 1], z = A[3 * il + 2];
        mx[k] = -2.0f * x;
        my[k] = -2.0f * y;
        mz[k] = -2.0f * z;
        ci[k] = fmaf(x, x, fmaf(y, y, z * z));
        cmin[k] = 3.4e38f;
#pragma unroll
        for (int m = 0; m < 6; ++m) h[k][m] = 3.4e38f;
    }

    // ---- Phase 1: Chamfer — min sq-dist to ori ----
    for (int t = 0; t < NTILE; ++t) {
        __syncthreads();
        const float* P = O + (size_t)(t * TILE_J) * 3;
        for (int j = tid; j < TILE_J; j += THREADS) {
            float x = P[3 * j + 0], y = P[3 * j + 1], z = P[3 * j + 2];
            s_x[j] = x; s_y[j] = y; s_z[j] = z;
            s_s[j] = fmaf(x, x, fmaf(y, y, z * z));
        }
        __syncthreads();

        const int jbeg = seg * JLEN;
#pragma unroll 1
        for (int j = jbeg; j < jbeg + JLEN; ++j) {
            float xj = s_x[j], yj = s_y[j], zj = s_z[j], sj = s_s[j];
#pragma unroll
            for (int k = 0; k < IPT; ++k) {
                float d = fmaf(mx[k], xj, sj + ci[k]);
                d = fmaf(my[k], yj, d);
                d = fmaf(mz[k], zj, d);
                cmin[k] = fminf(cmin[k], d);
            }
        }
    }

    // ---- Phase 2: kNN — 6 smallest sq-dist within adv (self included) ----
    for (int t = 0; t < NTILE; ++t) {
        __syncthreads();
        const float* P = A + (size_t)(t * TILE_J) * 3;
        for (int j = tid; j < TILE_J; j += THREADS) {
            float x = P[3 * j + 0], y = P[3 * j + 1], z = P[3 * j + 2];
            s_x[j] = x; s_y[j] = y; s_z[j] = z;
            s_s[j] = fmaf(x, x, fmaf(y, y, z * z));
        }
        __syncthreads();

        const int jbeg = seg * JLEN;
#pragma unroll 1
        for (int j = jbeg; j < jbeg + JLEN; ++j) {
            float xj = s_x[j], yj = s_y[j], zj = s_z[j], sj = s_s[j];
#pragma unroll
            for (int k = 0; k < IPT; ++k) {
                float d = fmaf(mx[k], xj, sj + ci[k]);
                d = fmaf(my[k], yj, d);
                d = fmaf(mz[k], zj, d);
                if (d < h[k][5]) heap_insert(h[k], d);
            }
        }
    }

    // ---- Merge the 4 j-segment lanes (lanes l^1, l^2) ----
    const unsigned full = 0xffffffffu;
#pragma unroll
    for (int off = 1; off <= 2; off <<= 1) {
#pragma unroll
        for (int k = 0; k < IPT; ++k) {
            cmin[k] = fminf(cmin[k], __shfl_xor_sync(full, cmin[k], off));
            float tmp[6];
#pragma unroll
            for (int m = 0; m < 6; ++m)
                tmp[m] = __shfl_xor_sync(full, h[k][m], off);
#pragma unroll
            for (int m = 0; m < 6; ++m)
                heap_insert(h[k], tmp[m]);
        }
    }

    if (seg == 0) {
#pragma unroll
        for (int k = 0; k < IPT; ++k) {
            int i = ibase + k;
            g_cham[b * KP + i] = cmin[k];
            // drop h[0] (self-distance), mean of remaining 5
            g_value[b * KP + i] =
                0.2f * (h[k][1] + h[k][2] + h[k][3] + h[k][4] + h[k][5]);
        }
    }
}

__device__ __forceinline__ float block_reduce_sum(float v, float* red) {
    const int tid = threadIdx.x;
    red[tid] = v;
    __syncthreads();
    for (int s = 128; s > 0; s >>= 1) {
        if (tid < s) red[tid] += red[tid + s];
        __syncthreads();
    }
    float r = red[0];
    __syncthreads();
    return r;
}

__global__ void __launch_bounds__(256)
reduce_kernel() {
    __shared__ float red[256];
    const int b = blockIdx.x;
    const int tid = threadIdx.x;
    const float* cham = g_cham + b * KP;
    const float* val  = g_value + b * KP;

    float s1 = 0.0f, s2 = 0.0f;
    for (int i = tid; i < KP; i += 256) { s1 += cham[i]; s2 += val[i]; }
    float cham_sum = block_reduce_sum(s1, red);
    float val_sum  = block_reduce_sum(s2, red);
    float mean = val_sum * (1.0f / KP);

    float s3 = 0.0f;
    for (int i = tid; i < KP; i += 256) {
        float d = val[i] - mean;
        s3 = fmaf(d, d, s3);
    }
    float var_sum = block_reduce_sum(s3, red);
    float stdv = sqrtf(var_sum * (1.0f / (KP - 1)));   // ddof=1
    float thr = fmaf(ALPHA, stdv, mean);

    float s4 = 0.0f;
    for (int i = tid; i < KP; i += 256) {
        float v = val[i];
        if (v > thr) s4 += v;
    }
    float msum = block_reduce_sum(s4, red);

    if (tid == 0) {
        float cham_mean = cham_sum * (1.0f / KP);
        float knn_mean  = msum * (1.0f / KP);
        g_batch[b] = cham_mean * W_CHAMFER + knn_mean * W_KNN;
    }
}

__global__ void final_kernel(float* __restrict__ out) {
    if (threadIdx.x == 0) {
        float s = 0.0f;
#pragma unroll
        for (int b = 0; b < BP; ++b) s += g_batch[b];
        out[0] = s * (1.0f / BP);
    }
}

extern "C" void kernel_launch(void* const* d_in, const int* in_sizes, int n_in,
                              void* d_out, int out_size) {
    const float* adv = (const float*)d_in[0];
    const float* ori = (const float*)d_in[1];
    float* out = (float*)d_out;

    dist_kernel<<<dim3(KP / TILE_I, BP), THREADS, SMEM_BYTES>>>(adv, ori);
    reduce_kernel<<<BP, 256>>>();
    final_kernel<<<1, 32>>>(out);
}

// round 3
// speedup vs baseline: 1.3832x; 1.3832x over previous
#include <cuda_runtime.h>
#include <math.h>

#define KP 4096
#define BP 8
#define THREADS 128          // 4 warps = 4 j-segments
#define TILE_I 128           // i-points per block
#define IPT 4                // i-points per thread (lane l owns i = ibase + l + 32k)
#define JSEG 4               // j-split across warps
#define TILE_J 1024          // j-points per smem tile
#define NTILE (KP / TILE_J)  // 4
#define JLEN (TILE_J / JSEG) // 256 j per warp per tile
#define JPAIRS (JLEN / 2)    // 128 packed pairs
#define SMEM_FLOATS (4 * TILE_J)
#define SMEM_BYTES (SMEM_FLOATS * 4)   // 16 KB

#define W_CHAMFER 5.0f
#define W_KNN 3.0f
#define ALPHA 1.05f

__device__ float g_cham[BP * KP];
__device__ float g_value[BP * KP];
__device__ float g_batch[BP];

typedef unsigned long long u64;

__device__ __forceinline__ u64 pk2(float lo, float hi) {
    u64 r;
    asm("mov.b64 %0, {%1, %2};" : "=l"(r) : "f"(lo), "f"(hi));
    return r;
}
__device__ __forceinline__ void upk2(u64 v, float& lo, float& hi) {
    asm("mov.b64 {%0, %1}, %2;" : "=f"(lo), "=f"(hi) : "l"(v));
}
__device__ __forceinline__ u64 ffma2(u64 a, u64 b, u64 c) {
    u64 d;
    asm("fma.rn.f32x2 %0, %1, %2, %3;" : "=l"(d) : "l"(a), "l"(b), "l"(c));
    return d;
}

// Insert d into ascending sorted 6-array (keeps 6 smallest).
__device__ __forceinline__ void heap_insert(float (&h)[6], float d) {
    if (d < h[5]) {
        h[5] = d;
#pragma unroll
        for (int m = 5; m >= 1; --m) {
            float lo = fminf(h[m - 1], h[m]);
            float hi = fmaxf(h[m - 1], h[m]);
            h[m - 1] = lo;
            h[m] = hi;
        }
    }
}

__global__ void __launch_bounds__(THREADS)
dist_kernel(const float* __restrict__ adv, const float* __restrict__ ori) {
    extern __shared__ float sm[];
    float* s_x = sm;
    float* s_y = sm + TILE_J;
    float* s_z = sm + 2 * TILE_J;
    float* s_s = sm + 3 * TILE_J;
    const float2* s_x2 = (const float2*)s_x;
    const float2* s_y2 = (const float2*)s_y;
    const float2* s_z2 = (const float2*)s_z;
    const float2* s_s2 = (const float2*)s_s;

    const int b   = blockIdx.y;
    const int tid = threadIdx.x;
    const int seg = tid >> 5;        // warp id = j-segment
    const int l   = tid & 31;        // lane
    const int ibase = blockIdx.x * TILE_I;
    const float* A = adv + (size_t)b * KP * 3;
    const float* O = ori + (size_t)b * KP * 3;

    // Per-thread i-points: i = ibase + l + 32*k
    u64 mx2[IPT], my2[IPT], mz2[IPT];
    float ci[IPT], cl[IPT], ch[IPT];
    float h[IPT][6];
#pragma unroll
    for (int k = 0; k < IPT; ++k) {
        int i = ibase + l + 32 * k;
        float x = A[3 * i + 0], y = A[3 * i + 1], z = A[3 * i + 2];
        float mx = -2.0f * x, my = -2.0f * y, mz = -2.0f * z;
        mx2[k] = pk2(mx, mx);
        my2[k] = pk2(my, my);
        mz2[k] = pk2(mz, mz);
        ci[k] = fmaf(x, x, fmaf(y, y, z * z));
        cl[k] = 3.4e38f; ch[k] = 3.4e38f;
#pragma unroll
        for (int m = 0; m < 6; ++m) h[k][m] = 3.4e38f;
    }

    // ---- Phase 1: Chamfer (min over ori). Distances EXCLUDE +ci (added at end). ----
    for (int t = 0; t < NTILE; ++t) {
        __syncthreads();
        const float* P = O + (size_t)(t * TILE_J) * 3;
        for (int j = tid; j < TILE_J; j += THREADS) {
            float x = P[3 * j + 0], y = P[3 * j + 1], z = P[3 * j + 2];
            s_x[j] = x; s_y[j] = y; s_z[j] = z;
            s_s[j] = fmaf(x, x, fmaf(y, y, z * z));
        }
        __syncthreads();

        const int pbeg = seg * JPAIRS;
#pragma unroll 2
        for (int p = pbeg; p < pbeg + JPAIRS; ++p) {
            float2 vx = s_x2[p], vy = s_y2[p], vz = s_z2[p], vs = s_s2[p];
            u64 xj = pk2(vx.x, vx.y), yj = pk2(vy.x, vy.y);
            u64 zj = pk2(vz.x, vz.y), sj = pk2(vs.x, vs.y);
#pragma unroll
            for (int k = 0; k < IPT; ++k) {
                u64 d = ffma2(mz2[k], zj, ffma2(my2[k], yj, ffma2(mx2[k], xj, sj)));
                float dl, dh;
                upk2(d, dl, dh);
                cl[k] = fminf(cl[k], dl);
                ch[k] = fminf(ch[k], dh);
            }
        }
    }

    // ---- Phase 2: kNN — 6 smallest within adv (self included; ci-offset dropped) ----
    for (int t = 0; t < NTILE; ++t) {
        __syncthreads();
        const float* P = A + (size_t)(t * TILE_J) * 3;
        for (int j = tid; j < TILE_J; j += THREADS) {
            float x = P[3 * j + 0], y = P[3 * j + 1], z = P[3 * j + 2];
            s_x[j] = x; s_y[j] = y; s_z[j] = z;
            s_s[j] = fmaf(x, x, fmaf(y, y, z * z));
        }
        __syncthreads();

        const int pbeg = seg * JPAIRS;
#pragma unroll 2
        for (int p = pbeg; p < pbeg + JPAIRS; ++p) {
            float2 vx = s_x2[p], vy = s_y2[p], vz = s_z2[p], vs = s_s2[p];
            u64 xj = pk2(vx.x, vx.y), yj = pk2(vy.x, vy.y);
            u64 zj = pk2(vz.x, vz.y), sj = pk2(vs.x, vs.y);
#pragma unroll
            for (int k = 0; k < IPT; ++k) {
                u64 d = ffma2(mz2[k], zj, ffma2(my2[k], yj, ffma2(mx2[k], xj, sj)));
                float dl, dh;
                upk2(d, dl, dh);
                if (fminf(dl, dh) < h[k][5]) {
                    heap_insert(h[k], dl);
                    heap_insert(h[k], dh);
                }
            }
        }
    }

    // Fold packed chamfer halves
    float cmin[IPT];
#pragma unroll
    for (int k = 0; k < IPT; ++k) cmin[k] = fminf(cl[k], ch[k]);

    // ---- Cross-warp merge (2-round tree), reusing tile smem as buffer ----
    // slot s: [(s*32 + l)*IPT + k]*7 + {cmin, h0..h5}
    float* buf = sm;
    __syncthreads();
    // round 1: segs 2,3 write slots 0,1
    if (seg >= 2) {
        float* w = buf + ((size_t)(seg - 2) * 32 + l) * IPT * 7;
#pragma unroll
        for (int k = 0; k < IPT; ++k) {
            w[k * 7 + 0] = cmin[k];
#pragma unroll
            for (int m = 0; m < 6; ++m) w[k * 7 + 1 + m] = h[k][m];
        }
    }
    __syncthreads();
    if (seg < 2) {
        const float* r = buf + ((size_t)seg * 32 + l) * IPT * 7;
#pragma unroll
        for (int k = 0; k < IPT; ++k) {
            cmin[k] = fminf(cmin[k], r[k * 7 + 0]);
#pragma unroll
            for (int m = 0; m < 6; ++m) heap_insert(h[k], r[k * 7 + 1 + m]);
        }
    }
    __syncthreads();
    // round 2: seg 1 writes slot 0; seg 0 merges
    if (seg == 1) {
        float* w = buf + (size_t)l * IPT * 7;
#pragma unroll
        for (int k = 0; k < IPT; ++k) {
            w[k * 7 + 0] = cmin[k];
#pragma unroll
            for (int m = 0; m < 6; ++m) w[k * 7 + 1 + m] = h[k][m];
        }
    }
    __syncthreads();
    if (seg == 0) {
        const float* r = buf + (size_t)l * IPT * 7;
#pragma unroll
        for (int k = 0; k < IPT; ++k) {
            cmin[k] = fminf(cmin[k], r[k * 7 + 0]);
#pragma unroll
            for (int m = 0; m < 6; ++m) heap_insert(h[k], r[k * 7 + 1 + m]);
            int i = ibase + l + 32 * k;
            g_cham[b * KP + i] = cmin[k] + ci[k];
            // drop h[0] (self), mean of next 5, re-add ci offset
            g_value[b * KP + i] =
                fmaf(0.2f, h[k][1] + h[k][2] + h[k][3] + h[k][4] + h[k][5], ci[k]);
        }
    }
}

__device__ __forceinline__ float block_reduce_sum(float v, float* red) {
    const int tid = threadIdx.x;
    red[tid] = v;
    __syncthreads();
    for (int s = 128; s > 0; s >>= 1) {
        if (tid < s) red[tid] += red[tid + s];
        __syncthreads();
    }
    float r = red[0];
    __syncthreads();
    return r;
}

__global__ void __launch_bounds__(256)
reduce_kernel() {
    __shared__ float red[256];
    const int b = blockIdx.x;
    const int tid = threadIdx.x;
    const float* cham = g_cham + b * KP;
    const float* val  = g_value + b * KP;

    float s1 = 0.0f, s2 = 0.0f;
    for (int i = tid; i < KP; i += 256) { s1 += cham[i]; s2 += val[i]; }
    float cham_sum = block_reduce_sum(s1, red);
    float val_sum  = block_reduce_sum(s2, red);
    float mean = val_sum * (1.0f / KP);

    float s3 = 0.0f;
    for (int i = tid; i < KP; i += 256) {
        float d = val[i] - mean;
        s3 = fmaf(d, d, s3);
    }
    float var_sum = block_reduce_sum(s3, red);
    float stdv = sqrtf(var_sum * (1.0f / (KP - 1)));   // ddof=1
    float thr = fmaf(ALPHA, stdv, mean);

    float s4 = 0.0f;
    for (int i = tid; i < KP; i += 256) {
        float v = val[i];
        if (v > thr) s4 += v;
    }
    float msum = block_reduce_sum(s4, red);

    if (tid == 0) {
        float cham_mean = cham_sum * (1.0f / KP);
        float knn_mean  = msum * (1.0f / KP);
        g_batch[b] = cham_mean * W_CHAMFER + knn_mean * W_KNN;
    }
}

__global__ void final_kernel(float* __restrict__ out) {
    if (threadIdx.x == 0) {
        float s = 0.0f;
#pragma unroll
        for (int b = 0; b < BP; ++b) s += g_batch[b];
        out[0] = s * (1.0f / BP);
    }
}

extern "C" void kernel_launch(void* const* d_in, const int* in_sizes, int n_in,
                              void* d_out, int out_size) {
    const float* adv = (const float*)d_in[0];
    const float* ori = (const float*)d_in[1];
    float* out = (float*)d_out;

    dist_kernel<<<dim3(KP / TILE_I, BP), THREADS, SMEM_BYTES>>>(adv, ori);
    reduce_kernel<<<BP, 256>>>();
    final_kernel<<<1, 32>>>(out);
}

// round 4
// speedup vs baseline: 2.0407x; 1.4754x over previous
#include <cuda_runtime.h>
#include <math.h>

#define KP 4096
#define BP 8
#define THREADS 256          // 8 warps = 8 j-segments
#define WARPS 8
#define TILE_I 64            // i-points per block
#define IPT 2                // i-points per thread (lane l owns i = ibase + l + 32k)
#define TILE_J 1024          // j-points per smem tile
#define NTILE (KP / TILE_J)  // 4
#define WPAIRS (TILE_J / 2 / WARPS)  // 64 packed pairs per warp per tile
#define SMEM_FLOATS (4 * TILE_J)
#define SMEM_BYTES (SMEM_FLOATS * 4)   // 16 KB

#define W_CHAMFER 5.0f
#define W_KNN 3.0f
#define ALPHA 1.05f

__device__ float g_cham[BP * KP];
__device__ float g_value[BP * KP];
__device__ float g_batch[BP];

typedef unsigned long long u64;

__device__ __forceinline__ u64 pk2(float lo, float hi) {
    u64 r;
    asm("mov.b64 %0, {%1, %2};" : "=l"(r) : "f"(lo), "f"(hi));
    return r;
}
__device__ __forceinline__ void upk2(u64 v, float& lo, float& hi) {
    asm("mov.b64 {%0, %1}, %2;" : "=f"(lo), "=f"(hi) : "l"(v));
}
__device__ __forceinline__ u64 ffma2(u64 a, u64 b, u64 c) {
    u64 d;
    asm("fma.rn.f32x2 %0, %1, %2, %3;" : "=l"(d) : "l"(a), "l"(b), "l"(c));
    return d;
}

// Insert d into ascending sorted 6-array (keeps 6 smallest).
__device__ __forceinline__ void heap_insert(float (&h)[6], float d) {
    if (d < h[5]) {
        h[5] = d;
#pragma unroll
        for (int m = 5; m >= 1; --m) {
            float lo = fminf(h[m - 1], h[m]);
            float hi = fmaxf(h[m - 1], h[m]);
            h[m - 1] = lo;
            h[m] = hi;
        }
    }
}

__global__ void __launch_bounds__(THREADS)
dist_kernel(const float* __restrict__ adv, const float* __restrict__ ori) {
    extern __shared__ float sm[];
    float* s_x = sm;
    float* s_y = sm + TILE_J;
    float* s_z = sm + 2 * TILE_J;
    float* s_s = sm + 3 * TILE_J;
    const u64* s_x2 = (const u64*)s_x;   // direct LDS.64 into packed pairs
    const u64* s_y2 = (const u64*)s_y;
    const u64* s_z2 = (const u64*)s_z;
    const u64* s_s2 = (const u64*)s_s;

    const int b   = blockIdx.y;
    const int tid = threadIdx.x;
    const int seg = tid >> 5;        // warp id = j-segment (0..7)
    const int l   = tid & 31;        // lane
    const int ibase = blockIdx.x * TILE_I;
    const float* A = adv + (size_t)b * KP * 3;
    const float* O = ori + (size_t)b * KP * 3;

    // Per-thread i-points: i = ibase + l + 32*k
    u64 mx2[IPT], my2[IPT], mz2[IPT];
    float ci[IPT], cl[IPT], ch[IPT];
    float h[IPT][6];
#pragma unroll
    for (int k = 0; k < IPT; ++k) {
        int i = ibase + l + 32 * k;
        float x = A[3 * i + 0], y = A[3 * i + 1], z = A[3 * i + 2];
        float mx = -2.0f * x, my = -2.0f * y, mz = -2.0f * z;
        mx2[k] = pk2(mx, mx);
        my2[k] = pk2(my, my);
        mz2[k] = pk2(mz, mz);
        ci[k] = fmaf(x, x, fmaf(y, y, z * z));
        cl[k] = 3.4e38f; ch[k] = 3.4e38f;
#pragma unroll
        for (int m = 0; m < 6; ++m) h[k][m] = 3.4e38f;
    }

    // ---- Phase 1: Chamfer (min over ori). Distances EXCLUDE +ci (added at end). ----
    for (int t = 0; t < NTILE; ++t) {
        __syncthreads();
        const float* P = O + (size_t)(t * TILE_J) * 3;
        for (int j = tid; j < TILE_J; j += THREADS) {
            float x = P[3 * j + 0], y = P[3 * j + 1], z = P[3 * j + 2];
            s_x[j] = x; s_y[j] = y; s_z[j] = z;
            s_s[j] = fmaf(x, x, fmaf(y, y, z * z));
        }
        __syncthreads();

        const int pbeg = seg * WPAIRS;
#pragma unroll 4
        for (int p = pbeg; p < pbeg + WPAIRS; ++p) {
            u64 xj = s_x2[p], yj = s_y2[p], zj = s_z2[p], sj = s_s2[p];
#pragma unroll
            for (int k = 0; k < IPT; ++k) {
                u64 d = ffma2(mz2[k], zj, ffma2(my2[k], yj, ffma2(mx2[k], xj, sj)));
                float dl, dh;
                upk2(d, dl, dh);
                cl[k] = fminf(cl[k], dl);
                ch[k] = fminf(ch[k], dh);
            }
        }
    }

    // ---- Phase 2: kNN — 6 smallest within adv (self included; ci-offset dropped) ----
    for (int t = 0; t < NTILE; ++t) {
        __syncthreads();
        const float* P = A + (size_t)(t * TILE_J) * 3;
        for (int j = tid; j < TILE_J; j += THREADS) {
            float x = P[3 * j + 0], y = P[3 * j + 1], z = P[3 * j + 2];
            s_x[j] = x; s_y[j] = y; s_z[j] = z;
            s_s[j] = fmaf(x, x, fmaf(y, y, z * z));
        }
        __syncthreads();

        const int pbeg = seg * WPAIRS;
#pragma unroll 4
        for (int p = pbeg; p < pbeg + WPAIRS; ++p) {
            u64 xj = s_x2[p], yj = s_y2[p], zj = s_z2[p], sj = s_s2[p];
#pragma unroll
            for (int k = 0; k < IPT; ++k) {
                u64 d = ffma2(mz2[k], zj, ffma2(my2[k], yj, ffma2(mx2[k], xj, sj)));
                float dl, dh;
                upk2(d, dl, dh);
                if (fminf(dl, dh) < h[k][5]) {
                    heap_insert(h[k], dl);
                    heap_insert(h[k], dh);
                }
            }
        }
    }

    // Fold packed chamfer halves
    float cmin[IPT];
#pragma unroll
    for (int k = 0; k < IPT; ++k) cmin[k] = fminf(cl[k], ch[k]);

    // ---- Cross-warp merge (3-round tree), reusing tile smem as buffer ----
    // slot s: [((s*32 + l)*IPT + k)*7] = {cmin, h0..h5}; max 4*32*2*7 = 1792 floats
    float* buf = sm;

#define MERGE_WRITE(SLOT)                                                   \
    {                                                                       \
        float* w = buf + (((size_t)(SLOT) * 32 + l) * IPT) * 7;             \
        _Pragma("unroll")                                                   \
        for (int k = 0; k < IPT; ++k) {                                     \
            w[k * 7 + 0] = cmin[k];                                         \
            _Pragma("unroll")                                               \
            for (int m = 0; m < 6; ++m) w[k * 7 + 1 + m] = h[k][m];         \
        }                                                                   \
    }
#define MERGE_READ(SLOT)                                                    \
    {                                                                       \
        const float* r = buf + (((size_t)(SLOT) * 32 + l) * IPT) * 7;       \
        _Pragma("unroll")                                                   \
        for (int k = 0; k < IPT; ++k) {                                     \
            cmin[k] = fminf(cmin[k], r[k * 7 + 0]);                         \
            _Pragma("unroll")                                               \
            for (int m = 0; m < 6; ++m) heap_insert(h[k], r[k * 7 + 1 + m]);\
        }                                                                   \
    }

    __syncthreads();
    if (seg >= 4) MERGE_WRITE(seg - 4);
    __syncthreads();
    if (seg < 4) MERGE_READ(seg);
    __syncthreads();
    if (seg == 2 || seg == 3) MERGE_WRITE(seg - 2);
    __syncthreads();
    if (seg < 2) MERGE_READ(seg);
    __syncthreads();
    if (seg == 1) MERGE_WRITE(0);
    __syncthreads();
    if (seg == 0) {
        MERGE_READ(0);
#pragma unroll
        for (int k = 0; k < IPT; ++k) {
            int i = ibase + l + 32 * k;
            g_cham[b * KP + i] = cmin[k] + ci[k];
            // drop h[0] (self), mean of next 5, re-add ci offset
            g_value[b * KP + i] =
                fmaf(0.2f, h[k][1] + h[k][2] + h[k][3] + h[k][4] + h[k][5], ci[k]);
        }
    }
}

__device__ __forceinline__ float block_reduce_sum(float v, float* red) {
    const int tid = threadIdx.x;
    red[tid] = v;
    __syncthreads();
    for (int s = 128; s > 0; s >>= 1) {
        if (tid < s) red[tid] += red[tid + s];
        __syncthreads();
    }
    float r = red[0];
    __syncthreads();
    return r;
}

__global__ void __launch_bounds__(256)
reduce_kernel() {
    __shared__ float red[256];
    const int b = blockIdx.x;
    const int tid = threadIdx.x;
    const float* cham = g_cham + b * KP;
    const float* val  = g_value + b * KP;

    float s1 = 0.0f, s2 = 0.0f;
    for (int i = tid; i < KP; i += 256) { s1 += cham[i]; s2 += val[i]; }
    float cham_sum = block_reduce_sum(s1, red);
    float val_sum  = block_reduce_sum(s2, red);
    float mean = val_sum * (1.0f / KP);

    float s3 = 0.0f;
    for (int i = tid; i < KP; i += 256) {
        float d = val[i] - mean;
        s3 = fmaf(d, d, s3);
    }
    float var_sum = block_reduce_sum(s3, red);
    float stdv = sqrtf(var_sum * (1.0f / (KP - 1)));   // ddof=1
    float thr = fmaf(ALPHA, stdv, mean);

    float s4 = 0.0f;
    for (int i = tid; i < KP; i += 256) {
        float v = val[i];
        if (v > thr) s4 += v;
    }
    float msum = block_reduce_sum(s4, red);

    if (tid == 0) {
        float cham_mean = cham_sum * (1.0f / KP);
        float knn_mean  = msum * (1.0f / KP);
        g_batch[b] = cham_mean * W_CHAMFER + knn_mean * W_KNN;
    }
}

__global__ void final_kernel(float* __restrict__ out) {
    if (threadIdx.x == 0) {
        float s = 0.0f;
#pragma unroll
        for (int b = 0; b < BP; ++b) s += g_batch[b];
        out[0] = s * (1.0f / BP);
    }
}

extern "C" void kernel_launch(void* const* d_in, const int* in_sizes, int n_in,
                              void* d_out, int out_size) {
    const float* adv = (const float*)d_in[0];
    const float* ori = (const float*)d_in[1];
    float* out = (float*)d_out;

    dist_kernel<<<dim3(KP / TILE_I, BP), THREADS, SMEM_BYTES>>>(adv, ori);
    reduce_kernel<<<BP, 256>>>();
    final_kernel<<<1, 32>>>(out);
}